// round 15
// baseline (speedup 1.0000x reference)
#include <cuda_runtime.h>
#include <cstdint>

// out[i,p] = sum_{m,n} A[i,m] * B[i,n] * C[m,n,p]   (M1=M2=MP=5)
//
// Round-15 = round-14 compute (p-axis packed FFMA2, pre-packed constant C,
// 42-reg cap, 6 CTAs/SM = 48 warps) + warp-scoped smem transpose so ALL
// global traffic is coalesced. Round-14's dur matched the L1tex wavefront
// model exactly (75 wf/warp from 20B-strided LDG/STG.32); transposing via
// per-warp smem cuts it to 15 gmem wf + 30 conflict-free smem accesses.
// No CTA barriers: each warp owns a private 320-float buffer pair.

#define M1 5
#define M2 5
#define MP 5
#define TPB 256
#define NWARP (TPB / 32)
#define NPAIR 3                          // p-pairs: (0,1) (2,3) (4,zero)
#define CPK_FLOATS (M1 * NPAIR * 8 * 2)  // 240

__constant__ __align__(16) float cCd[CPK_FLOATS];
__device__ __align__(16) float g_scratch[CPK_FLOATS];

typedef unsigned long long u64;

__device__ __forceinline__ u64 pack2(float lo, float hi) {
    u64 r; asm("mov.b64 %0, {%1, %2};" : "=l"(r) : "f"(lo), "f"(hi)); return r;
}
__device__ __forceinline__ void unpack2(u64 v, float& lo, float& hi) {
    asm("mov.b64 {%0, %1}, %2;" : "=f"(lo), "=f"(hi) : "l"(v));
}
__device__ __forceinline__ u64 fma2(u64 a, u64 b, u64 c) {
    u64 r; asm("fma.rn.f32x2 %0, %1, %2, %3;" : "=l"(r) : "l"(a), "l"(b), "l"(c)); return r;
}
__device__ __forceinline__ u64 mul2(u64 a, u64 b) {
    u64 r; asm("mul.rn.f32x2 %0, %1, %2;" : "=l"(r) : "l"(a), "l"(b)); return r;
}

__global__ void pack_C_kernel(const float* __restrict__ C) {
    int idx = threadIdx.x;               // 240 slots, one block of 256
    if (idx < CPK_FLOATS) {
        int lane = idx & 1;
        int q    = idx >> 1;             // (m*3 + pr)*8 + n
        int n    = q & 7;
        int mp   = q >> 3;               // m*3 + pr
        int pr   = mp % 3;
        int m    = mp / 3;
        int p    = pr * 2 + lane;        // pr=2,lane=1 -> p=5: zero pad
        float v  = 0.0f;
        if (n < M2 && p < MP) v = C[(m * M2 + n) * MP + p];
        g_scratch[idx] = v;
    }
}

__global__ __launch_bounds__(TPB, 6)
void cg_combine_kernel(const float* __restrict__ A,
                       const float* __restrict__ B,
                       float* __restrict__ out,
                       long long n_edges)
{
    // per-warp private buffers: [0:160) = A-chunk / results, [160:320) = B-chunk
    __shared__ float sbuf[NWARP][320];

    int t    = threadIdx.x;
    int lane = t & 31;
    int w    = t >> 5;
    float* sA = &sbuf[w][0];
    float* sB = &sbuf[w][160];

    long long warp_e0 = (long long)blockIdx.x * TPB + (w << 5);  // 32 edges/warp

    if (warp_e0 + 32 <= n_edges) {
        size_t gbase = (size_t)warp_e0 * 5;      // 160 floats per array

        // ---- coalesced loads: 10x LDG.32, 1 wavefront each ----
        float ra[5], rb[5];
#pragma unroll
        for (int i = 0; i < 5; i++) ra[i] = __ldcs(A + gbase + lane + 32 * i);
#pragma unroll
        for (int i = 0; i < 5; i++) rb[i] = __ldcs(B + gbase + lane + 32 * i);
#pragma unroll
        for (int i = 0; i < 5; i++) { sA[lane + 32 * i] = ra[i]; sB[lane + 32 * i] = rb[i]; }
        __syncwarp();

        // ---- per-edge reads: stride-5 (gcd(5,32)=1 -> conflict-free) ----
        float b0 = sB[lane * 5 + 0], b1 = sB[lane * 5 + 1], b2 = sB[lane * 5 + 2],
              b3 = sB[lane * 5 + 3], b4 = sB[lane * 5 + 4];
        u64 bp0 = pack2(b0, b0), bp1 = pack2(b1, b1), bp2 = pack2(b2, b2),
            bp3 = pack2(b3, b3), bp4 = pack2(b4, b4);

        u64 acc[NPAIR];
#pragma unroll
        for (int i = 0; i < NPAIR; i++) acc[i] = 0ULL;

#pragma unroll
        for (int m = 0; m < M1; m++) {
            float am = sA[lane * 5 + m];         // own slots: no hazard
            u64 amp = pack2(am, am);
#pragma unroll
            for (int pr = 0; pr < NPAIR; pr++) {
                const float* col = &cCd[((m * NPAIR + pr) * 8) * 2];
                const ulonglong2 c01 = *reinterpret_cast<const ulonglong2*>(col + 0);
                const ulonglong2 c23 = *reinterpret_cast<const ulonglong2*>(col + 4);
                const u64        c4  = *reinterpret_cast<const u64*>(col + 8);

                u64 d = mul2(c01.x, bp0);
                d = fma2(bp1, c01.y, d);
                d = fma2(bp2, c23.x, d);
                d = fma2(bp3, c23.y, d);
                d = fma2(bp4, c4,    d);

                acc[pr] = fma2(amp, d, acc[pr]);
            }
        }

        // ---- transpose results back: own-slot STS (no sync needed before) ----
        float o0, o1, o2, o3, o4, dead;
        unpack2(acc[0], o0, o1);
        unpack2(acc[1], o2, o3);
        unpack2(acc[2], o4, dead);
        sA[lane * 5 + 0] = o0;
        sA[lane * 5 + 1] = o1;
        sA[lane * 5 + 2] = o2;
        sA[lane * 5 + 3] = o3;
        sA[lane * 5 + 4] = o4;
        __syncwarp();

        // ---- coalesced stores: 5x STG.32, 1 wavefront each ----
#pragma unroll
        for (int i = 0; i < 5; i++)
            __stcs(out + gbase + lane + 32 * i, sA[lane + 32 * i]);
    } else {
        // ---- tail warp (warp-uniform; not taken for N = 16,777,216) ----
        long long e = warp_e0 + lane;
        if (e < n_edges) {
            size_t base = (size_t)e * 5;
            float a[5], b[5];
#pragma unroll
            for (int k = 0; k < 5; k++) { a[k] = A[base + k]; b[k] = B[base + k]; }
#pragma unroll
            for (int p = 0; p < MP; p++) {
                float s = 0.0f;
#pragma unroll
                for (int m = 0; m < M1; m++) {
                    float d = 0.0f;
#pragma unroll
                    for (int n = 0; n < M2; n++) {
                        int pr = p >> 1, ln = p & 1;
                        d = fmaf(b[n], cCd[(((m * NPAIR + pr) * 8 + n) << 1) + ln], d);
                    }
                    s = fmaf(a[m], d, s);
                }
                out[base + p] = s;
            }
        }
    }
}

extern "C" void kernel_launch(void* const* d_in, const int* in_sizes, int n_in,
                              void* d_out, int out_size)
{
    const float* A = (const float*)d_in[0];
    const float* B = (const float*)d_in[1];
    const float* C = (const float*)d_in[2];
    float* out = (float*)d_out;

    // Prep: pack C into p-pairs in __device__ scratch, then copy into the
    // constant bank. Graph-capturable stream-0 nodes; stream order makes the
    // constant data visible to the main kernel.
    pack_C_kernel<<<1, TPB>>>(C);
    void* scratch_ptr = nullptr;
    cudaGetSymbolAddress(&scratch_ptr, g_scratch);
    cudaMemcpyToSymbolAsync(cCd, scratch_ptr, CPK_FLOATS * sizeof(float), 0,
                            cudaMemcpyDeviceToDevice, 0);

    long long n_edges = (long long)in_sizes[0] / M1;
    int blocks = (int)((n_edges + TPB - 1) / TPB);

    cg_combine_kernel<<<blocks, TPB>>>(A, B, out, n_edges);
}

// round 16
// speedup vs baseline: 1.0537x; 1.0537x over previous
#include <cuda_runtime.h>
#include <cstdint>

// out[i,p] = sum_{m,n} A[i,m] * B[i,n] * C[m,n,p]   (M1=M2=MP=5)
//
// Round-16 = round-14 body VERBATIM (EPT=1, front-batched LDG.32, p-axis
// packed FFMA2, pre-packed constant-bank C) with the occupancy cap moved
// from 6 to 7 CTAs/SM: __launch_bounds__(256,7) -> 36-reg cap -> 56 warps.
// Round-14 compiled to 40 regs under a 42 cap with peak-live ~36-39; a 36
// cap asks ptxas for a ~10% squeeze (narrower C-load windows), unlike the
// failed 48/32-cap rounds that demanded 20-40%. Round-15 (smem transpose)
// regressed and is abandoned; round-14 at DRAM 83%/occ 63% is latency-
// exposed — more warps is the remaining lever.

#define M1 5
#define M2 5
#define MP 5
#define TPB 256
#define NPAIR 3                          // p-pairs: (0,1) (2,3) (4,zero)
// packed C: cCd[((m*3 + pr)*8 + n)*2 + lane], lane0=p_lo, lane1=p_hi
#define CPK_FLOATS (M1 * NPAIR * 8 * 2)  // 240

__constant__ __align__(16) float cCd[CPK_FLOATS];
__device__ __align__(16) float g_scratch[CPK_FLOATS];

typedef unsigned long long u64;

__device__ __forceinline__ u64 pack2(float lo, float hi) {
    u64 r; asm("mov.b64 %0, {%1, %2};" : "=l"(r) : "f"(lo), "f"(hi)); return r;
}
__device__ __forceinline__ void unpack2(u64 v, float& lo, float& hi) {
    asm("mov.b64 {%0, %1}, %2;" : "=f"(lo), "=f"(hi) : "l"(v));
}
__device__ __forceinline__ u64 fma2(u64 a, u64 b, u64 c) {
    u64 r; asm("fma.rn.f32x2 %0, %1, %2, %3;" : "=l"(r) : "l"(a), "l"(b), "l"(c)); return r;
}
__device__ __forceinline__ u64 mul2(u64 a, u64 b) {
    u64 r; asm("mul.rn.f32x2 %0, %1, %2;" : "=l"(r) : "l"(a), "l"(b)); return r;
}

__global__ void pack_C_kernel(const float* __restrict__ C) {
    int idx = threadIdx.x;               // 240 slots, one block of 256
    if (idx < CPK_FLOATS) {
        int lane = idx & 1;
        int q    = idx >> 1;             // (m*3 + pr)*8 + n
        int n    = q & 7;
        int mp   = q >> 3;               // m*3 + pr
        int pr   = mp % 3;
        int m    = mp / 3;
        int p    = pr * 2 + lane;        // pr=2,lane=1 -> p=5: zero pad
        float v  = 0.0f;
        if (n < M2 && p < MP) v = C[(m * M2 + n) * MP + p];
        g_scratch[idx] = v;
    }
}

__global__ __launch_bounds__(TPB, 7)
void cg_combine_kernel(const float* __restrict__ A,
                       const float* __restrict__ B,
                       float* __restrict__ out,
                       long long n_edges)
{
    long long e = (long long)blockIdx.x * TPB + threadIdx.x;
    if (e >= n_edges) return;

    size_t base = (size_t)e * 5;

    // ---- front-batched loads: 10x LDG.32 ----
    const float* pa = A + base;
    const float* pb = B + base;
    float a0 = __ldcs(pa + 0), a1 = __ldcs(pa + 1), a2 = __ldcs(pa + 2),
          a3 = __ldcs(pa + 3), a4 = __ldcs(pa + 4);
    float b0 = __ldcs(pb + 0), b1 = __ldcs(pb + 1), b2 = __ldcs(pb + 2),
          b3 = __ldcs(pb + 3), b4 = __ldcs(pb + 4);

    // duplicate b into packed pairs (persistent, 5 x u64)
    u64 bp0 = pack2(b0, b0), bp1 = pack2(b1, b1), bp2 = pack2(b2, b2),
        bp3 = pack2(b3, b3), bp4 = pack2(b4, b4);

    u64 acc[NPAIR];
#pragma unroll
    for (int i = 0; i < NPAIR; i++) acc[i] = 0ULL;

#pragma unroll
    for (int m = 0; m < M1; m++) {
        float am;
        switch (m) {
            case 0: am = a0; break;
            case 1: am = a1; break;
            case 2: am = a2; break;
            case 3: am = a3; break;
            default: am = a4; break;
        }
        u64 amp = pack2(am, am);         // transient pair

#pragma unroll
        for (int pr = 0; pr < NPAIR; pr++) {
            const float* col = &cCd[((m * NPAIR + pr) * 8) * 2];
            // 5 packed C values: 2x LDC.128 + 1x LDC.64 (const port, off L1)
            const ulonglong2 c01 = *reinterpret_cast<const ulonglong2*>(col + 0);
            const ulonglong2 c23 = *reinterpret_cast<const ulonglong2*>(col + 4);
            const u64        c4  = *reinterpret_cast<const u64*>(col + 8);

            u64 d = mul2(c01.x, bp0);
            d = fma2(bp1, c01.y, d);
            d = fma2(bp2, c23.x, d);
            d = fma2(bp3, c23.y, d);
            d = fma2(bp4, c4,    d);

            acc[pr] = fma2(amp, d, acc[pr]);
        }
    }

    // ---- epilogue: unpack (register-pair movs) + 5 scalar STG.32 ----
    float o0, o1, o2, o3, o4, dead;
    unpack2(acc[0], o0, o1);
    unpack2(acc[1], o2, o3);
    unpack2(acc[2], o4, dead);

    float* po = out + base;
    __stcs(po + 0, o0);
    __stcs(po + 1, o1);
    __stcs(po + 2, o2);
    __stcs(po + 3, o3);
    __stcs(po + 4, o4);
}

extern "C" void kernel_launch(void* const* d_in, const int* in_sizes, int n_in,
                              void* d_out, int out_size)
{
    const float* A = (const float*)d_in[0];
    const float* B = (const float*)d_in[1];
    const float* C = (const float*)d_in[2];
    float* out = (float*)d_out;

    // Prep: pack C into p-pairs in __device__ scratch, then copy into the
    // constant bank. Graph-capturable stream-0 nodes; stream order makes the
    // constant data visible to the main kernel.
    pack_C_kernel<<<1, TPB>>>(C);
    void* scratch_ptr = nullptr;
    cudaGetSymbolAddress(&scratch_ptr, g_scratch);
    cudaMemcpyToSymbolAsync(cCd, scratch_ptr, CPK_FLOATS * sizeof(float), 0,
                            cudaMemcpyDeviceToDevice, 0);

    long long n_edges = (long long)in_sizes[0] / M1;
    int blocks = (int)((n_edges + TPB - 1) / TPB);

    cg_combine_kernel<<<blocks, TPB>>>(A, B, out, n_edges);
}